// round 8
// baseline (speedup 1.0000x reference)
#include <cuda_runtime.h>

#define NMAX 100000
#define EMAX 1600000
#define NLYR 3

// Device scratch.
__device__ __align__(16) float g_all[(size_t)NMAX * 512];
__device__ __align__(16) float g_ego[(size_t)NMAX * 128];
__device__ __align__(16) float g_msg[(size_t)NMAX * 128];
__device__ __align__(16) float g_wPack[NLYR * 256 * 128];
// CSR built once per launch, reused by all 3 layers.
__device__ int   g_rowptr[NMAX];
__device__ int   g_cnt[NMAX];
__device__ int   g_off[NMAX];
__device__ int   g_total;
__device__ int   g_ecol[EMAX];
__device__ float g_ewc[EMAX];

// packed f32x2 fma: d = a*b + d
__device__ __forceinline__ void fma2(unsigned long long& d,
                                     unsigned long long a,
                                     unsigned long long b) {
    asm("fma.rn.f32x2 %0, %1, %2, %0;" : "+l"(d) : "l"(a), "l"(b));
}
__device__ __forceinline__ unsigned long long pack2(float a) {
    unsigned long long r;
    asm("mov.b64 %0, {%1, %1};" : "=l"(r) : "f"(a));
    return r;
}
__device__ __forceinline__ float lo32(unsigned long long x) {
    return __uint_as_float((unsigned)(x & 0xffffffffu));
}
__device__ __forceinline__ float hi32(unsigned long long x) {
    return __uint_as_float((unsigned)(x >> 32));
}

// ---------------------------------------------------------------------------
__global__ void pack_weights(const float* __restrict__ gw,
                             const float* __restrict__ bw) {
    int idx = blockIdx.x * blockDim.x + threadIdx.x;
    if (idx >= NLYR * 256 * 128) return;
    int l  = idx >> 15;
    int r  = idx & 32767;
    int k  = r >> 7;
    int od = r & 127;
    float v = (k < 128) ? gw[l * 16384 + od * 128 + k]
                        : bw[l * 16384 + od * 128 + (k - 128)];
    g_wPack[idx] = v;
}

// ---------------------------------------------------------------------------
__global__ void init_copy(const float4* __restrict__ emb4, int n) {
    int i = blockIdx.x * blockDim.x + threadIdx.x;
    if (i >= n * 32) return;
    int node = i >> 5, d4 = i & 31;
    float4 v = emb4[i];
    ((float4*)g_all)[(size_t)node * 128 + d4] = v;
    ((float4*)g_ego)[i] = v;
    if (d4 == 0) { g_cnt[node] = 0; g_off[node] = 0; }
    if (i == 0) g_total = 0;
}

// ---------------------------------------------------------------------------
// CSR build: histogram -> hierarchical offset reservation -> scatter.
// ---------------------------------------------------------------------------
__global__ void csr_hist(const int* __restrict__ ei, int E) {
    int e = blockIdx.x * blockDim.x + threadIdx.x;
    if (e < E) atomicAdd(&g_cnt[ei[e]], 1);
}

__global__ __launch_bounds__(256) void csr_offsets(int n) {
    __shared__ int wbase[8];
    int tid  = threadIdx.x;
    int lane = tid & 31;
    int w    = tid >> 5;
    int i    = blockIdx.x * 256 + tid;
    int cnt  = (i < n) ? g_cnt[i] : 0;

    int pre = cnt;
#pragma unroll
    for (int off = 1; off < 32; off <<= 1) {
        int v = __shfl_up_sync(0xffffffffu, pre, off);
        if (lane >= off) pre += v;
    }
    if (lane == 31) wbase[w] = pre;
    __syncthreads();

    if (w == 0) {
        int orig = (lane < 8) ? wbase[lane] : 0;
        int s = orig;
#pragma unroll
        for (int off = 1; off < 8; off <<= 1) {
            int v = __shfl_up_sync(0xffffffffu, s, off);
            if (lane >= off) s += v;
        }
        int total = __shfl_sync(0xffffffffu, s, 7);
        int base = 0;
        if (lane == 7) base = atomicAdd(&g_total, total);
        base = __shfl_sync(0xffffffffu, base, 7);
        if (lane < 8) wbase[lane] = base + s - orig;
    }
    __syncthreads();

    if (i < n) g_rowptr[i] = wbase[w] + pre - cnt;
}

__global__ void csr_scatter(const int* __restrict__ ei,
                            const float* __restrict__ ew, int E) {
    int e = blockIdx.x * blockDim.x + threadIdx.x;
    if (e >= E) return;
    int row = ei[e];
    int col = ei[E + e];
    int pos = g_rowptr[row] + atomicAdd(&g_off[row], 1);
    g_ecol[pos] = col;
    g_ewc[pos]  = ew[e];
}

// ---------------------------------------------------------------------------
// SpMM via CSR: one warp per row, register accumulation, zero atomics.
// ---------------------------------------------------------------------------
__global__ void spmm_csr(int n) {
    int gt = blockIdx.x * blockDim.x + threadIdx.x;
    int row = gt >> 5, lane = gt & 31;
    if (row >= n) return;
    int beg = g_rowptr[row];
    int end = beg + g_cnt[row];
    float4 acc = make_float4(0.f, 0.f, 0.f, 0.f);
    for (int b = beg; b < end; b += 32) {
        int idx = b + lane;
        int c = 0; float w = 0.f;
        if (idx < end) { c = g_ecol[idx]; w = g_ewc[idx]; }
        int m = min(32, end - b);
        for (int j = 0; j < m; ++j) {
            int   cc = __shfl_sync(0xffffffffu, c, j);
            float ww = __shfl_sync(0xffffffffu, w, j);
            float4 v = ((const float4*)g_ego)[(size_t)cc * 32 + lane];
            acc.x += ww * v.x; acc.y += ww * v.y;
            acc.z += ww * v.z; acc.w += ww * v.w;
        }
    }
    ((float4*)g_msg)[(size_t)row * 32 + lane] = acc;
}

// ---------------------------------------------------------------------------
// Fused layer GEMM, broadcast-B / lane-distinct-A, f32x2.
//   Tile: 128 nodes x 128 ods per block (512 thr, 16 warps).
//   Warp w -> ods [8w, 8w+8); lane l -> nodes {l, l+32, l+64, l+96}.
//   Per warp-k: 2 broadcast LDS.128 (B) + 4 LDS.32 (A) + 4 packs + 16 FFMA2
//   -> 6 smem wavefronts per 32 fma-pipe cycles: fma-bound.
// ---------------------------------------------------------------------------
#define AP 129   // As row pitch: 4*AP mod 32 = 4 -> conflict-free fill
__global__ __launch_bounds__(512) void fused_layer(
        const float* __restrict__ gcb, const float* __restrict__ bib,
        int n, int layer) {
    __shared__ __align__(16) float As[32 * AP];    // [kc][node]  ~16.5KB
    __shared__ __align__(16) float Bs[32 * 128];   // [kc][od]     16KB
    __shared__ float invS[128];

    const int tid  = threadIdx.x;
    const int lane = tid & 31;
    const int w    = tid >> 5;         // 0..15
    const int odb  = w * 8;
    const int nb   = blockIdx.x * 128;
    const int loff = layer * 128;
    const float* wP = g_wPack + layer * 32768;

    // A-fill task (2 iterations of 512 tasks cover 128 nodes x 8 k-quads)
    const int fk4 = tid & 7;           // k quad within chunk
    const int fn0 = tid >> 3;          // node 0..63

    unsigned long long acc[4][4];
#pragma unroll
    for (int i = 0; i < 4; ++i)
#pragma unroll
        for (int j = 0; j < 4; ++j) acc[i][j] = 0ull;

    for (int c = 0; c < 8; ++c) {
        __syncthreads();
        // --- B fill: 1024 float4 over 512 threads, coalesced
        {
            const float4* src = (const float4*)(wP + c * 32 * 128);
            float4* dst = (float4*)Bs;
            dst[tid]       = src[tid];
            dst[tid + 512] = src[tid + 512];
        }
        // --- A fill: 2 float4 loads per thread, transposed to As[k][node]
        {
            int kk = c * 32 + fk4 * 4;
#pragma unroll
            for (int i = 0; i < 2; ++i) {
                int node = fn0 + 64 * i;
                int g    = nb + node;
                float4 m = make_float4(0.f, 0.f, 0.f, 0.f);
                if (g < n) {
                    if (kk < 128) {
                        m = *(const float4*)(g_msg + (size_t)g * 128 + kk);
                    } else {
                        m = *(const float4*)(g_msg + (size_t)g * 128 + kk - 128);
                        float4 e = *(const float4*)(g_ego + (size_t)g * 128 + kk - 128);
                        m.x *= e.x; m.y *= e.y; m.z *= e.z; m.w *= e.w;
                    }
                }
                float* base = As + (fk4 * 4) * AP + node;
                base[0]      = m.x;
                base[AP]     = m.y;
                base[2 * AP] = m.z;
                base[3 * AP] = m.w;
            }
        }
        __syncthreads();
        // --- compute 32 k-steps
#pragma unroll 4
        for (int k = 0; k < 32; ++k) {
            const float* Ak = As + k * AP + lane;
            const ulonglong2* Bu = (const ulonglong2*)(Bs + k * 128 + odb);
            ulonglong2 b0 = Bu[0];     // ods odb..odb+3 (warp-uniform)
            ulonglong2 b1 = Bu[1];     // ods odb+4..odb+7
            unsigned long long p0 = pack2(Ak[0]);
            unsigned long long p1 = pack2(Ak[32]);
            unsigned long long p2 = pack2(Ak[64]);
            unsigned long long p3 = pack2(Ak[96]);
            fma2(acc[0][0], p0, b0.x); fma2(acc[0][1], p0, b0.y);
            fma2(acc[0][2], p0, b1.x); fma2(acc[0][3], p0, b1.y);
            fma2(acc[1][0], p1, b0.x); fma2(acc[1][1], p1, b0.y);
            fma2(acc[1][2], p1, b1.x); fma2(acc[1][3], p1, b1.y);
            fma2(acc[2][0], p2, b0.x); fma2(acc[2][1], p2, b0.y);
            fma2(acc[2][2], p2, b1.x); fma2(acc[2][3], p2, b1.y);
            fma2(acc[3][0], p3, b0.x); fma2(acc[3][1], p3, b0.y);
            fma2(acc[3][2], p3, b1.x); fma2(acc[3][3], p3, b1.y);
        }
    }

    // --- epilogue: bias, leaky_relu, cross-warp L2 norm, stores ---
    float bias[8];
    {
        float4 bg0 = *(const float4*)(gcb + loff + odb);
        float4 bg1 = *(const float4*)(gcb + loff + odb + 4);
        float4 bb0 = *(const float4*)(bib + loff + odb);
        float4 bb1 = *(const float4*)(bib + loff + odb + 4);
        bias[0] = bg0.x + bb0.x; bias[1] = bg0.y + bb0.y;
        bias[2] = bg0.z + bb0.z; bias[3] = bg0.w + bb0.w;
        bias[4] = bg1.x + bb1.x; bias[5] = bg1.y + bb1.y;
        bias[6] = bg1.z + bb1.z; bias[7] = bg1.w + bb1.w;
    }

    float v[4][8];
    float s[4];
#pragma unroll
    for (int nn = 0; nn < 4; ++nn) {
        float sum = 0.f;
#pragma unroll
        for (int j = 0; j < 4; ++j) {
            float x0 = lo32(acc[nn][j]) + bias[2 * j];
            float x1 = hi32(acc[nn][j]) + bias[2 * j + 1];
            x0 = (x0 > 0.f) ? x0 : 0.2f * x0;
            x1 = (x1 > 0.f) ? x1 : 0.2f * x1;
            v[nn][2 * j]     = x0;
            v[nn][2 * j + 1] = x1;
            sum += x0 * x0 + x1 * x1;
        }
        s[nn] = sum;
    }

    // cross-warp reduction: reuse As as red[16][128]
    __syncthreads();
#pragma unroll
    for (int nn = 0; nn < 4; ++nn)
        As[w * 128 + 32 * nn + lane] = s[nn];
    __syncthreads();
    if (tid < 128) {
        float t = 0.f;
#pragma unroll
        for (int ww = 0; ww < 16; ++ww) t += As[ww * 128 + tid];
        invS[tid] = 1.0f / fmaxf(sqrtf(t), 1e-12f);
    }
    __syncthreads();

#pragma unroll
    for (int nn = 0; nn < 4; ++nn) {
        int node = lane + 32 * nn;
        int g = nb + node;
        if (g < n) {
            float inv = invS[node];
            float4 w0 = make_float4(v[nn][0], v[nn][1], v[nn][2], v[nn][3]);
            float4 w1 = make_float4(v[nn][4], v[nn][5], v[nn][6], v[nn][7]);
            *(float4*)(g_ego + (size_t)g * 128 + odb)     = w0;
            *(float4*)(g_ego + (size_t)g * 128 + odb + 4) = w1;
            *(float4*)(g_all + (size_t)g * 512 + loff + 128 + odb) =
                make_float4(w0.x * inv, w0.y * inv, w0.z * inv, w0.w * inv);
            *(float4*)(g_all + (size_t)g * 512 + loff + 128 + odb + 4) =
                make_float4(w1.x * inv, w1.y * inv, w1.z * inv, w1.w * inv);
        }
    }
}

// ---------------------------------------------------------------------------
// Scoring: out[q] = dot(all[src[q]], all[dst[q]]) over 512 dims. Warp/query.
// ---------------------------------------------------------------------------
__global__ void score(const int* __restrict__ eli, int Q,
                      float* __restrict__ out) {
    int gt = blockIdx.x * blockDim.x + threadIdx.x;
    int q = gt >> 5, lane = gt & 31;
    if (q >= Q) return;
    int s = eli[q];
    int d = eli[Q + q];
    const float4* a = (const float4*)(g_all + (size_t)s * 512);
    const float4* b = (const float4*)(g_all + (size_t)d * 512);
    float acc = 0.f;
#pragma unroll
    for (int j = 0; j < 4; ++j) {
        float4 x = a[lane + 32 * j];
        float4 y = b[lane + 32 * j];
        acc += x.x * y.x + x.y * y.y + x.z * y.z + x.w * y.w;
    }
#pragma unroll
    for (int off = 16; off; off >>= 1)
        acc += __shfl_xor_sync(0xffffffffu, acc, off);
    if (lane == 0) out[q] = acc;
}

// ---------------------------------------------------------------------------
extern "C" void kernel_launch(void* const* d_in, const int* in_sizes, int n_in,
                              void* d_out, int out_size) {
    const int*   ei  = (const int*)d_in[0];
    const int*   eli = (const int*)d_in[1];
    const float* ew  = (const float*)d_in[2];
    const float* emb = (const float*)d_in[3];
    const float* gcw = (const float*)d_in[4];
    const float* gcb = (const float*)d_in[5];
    const float* biw = (const float*)d_in[6];
    const float* bib = (const float*)d_in[7];

    int E = in_sizes[0] / 2;
    int Q = in_sizes[1] / 2;
    int n = in_sizes[3] / 128;
    float* out = (float*)d_out;

    pack_weights<<<(NLYR * 256 * 128 + 255) / 256, 256>>>(gcw, biw);
    init_copy<<<(n * 32 + 255) / 256, 256>>>((const float4*)emb, n);

    csr_hist<<<(E + 255) / 256, 256>>>(ei, E);
    csr_offsets<<<(n + 255) / 256, 256>>>(n);
    csr_scatter<<<(E + 255) / 256, 256>>>(ei, ew, E);

    for (int l = 0; l < NLYR; ++l) {
        spmm_csr<<<(int)(((size_t)n * 32 + 255) / 256), 256>>>(n);
        fused_layer<<<(n + 127) / 128, 512>>>(gcb, bib, n, l);
    }

    score<<<(int)(((size_t)Q * 32 + 255) / 256), 256>>>(eli, Q, out);
}

// round 9
// speedup vs baseline: 1.1647x; 1.1647x over previous
#include <cuda_runtime.h>

#define NMAX 100000
#define EMAX 1600000
#define NLYR 3

// Device scratch.
__device__ __align__(16) float g_all[(size_t)NMAX * 512];
__device__ __align__(16) float g_ego[(size_t)NMAX * 128];
__device__ __align__(16) float g_msg[(size_t)NMAX * 128];
__device__ __align__(16) float g_wPack[NLYR * 256 * 128];
// CSR built once per launch, reused by all 3 layers.
__device__ int   g_rowptr[NMAX];
__device__ int   g_cnt[NMAX];
__device__ int   g_off[NMAX];
__device__ int   g_total;
__device__ int   g_ecol[EMAX];
__device__ float g_ewc[EMAX];

// packed f32x2 fma: d = a*b + d
__device__ __forceinline__ void fma2(unsigned long long& d,
                                     unsigned long long a,
                                     unsigned long long b) {
    asm("fma.rn.f32x2 %0, %1, %2, %0;" : "+l"(d) : "l"(a), "l"(b));
}
__device__ __forceinline__ unsigned long long pack2(float a) {
    unsigned long long r;
    asm("mov.b64 %0, {%1, %1};" : "=l"(r) : "f"(a));
    return r;
}
__device__ __forceinline__ float lo32(unsigned long long x) {
    return __uint_as_float((unsigned)(x & 0xffffffffu));
}
__device__ __forceinline__ float hi32(unsigned long long x) {
    return __uint_as_float((unsigned)(x >> 32));
}

// ---------------------------------------------------------------------------
__global__ void pack_weights(const float* __restrict__ gw,
                             const float* __restrict__ bw) {
    int idx = blockIdx.x * blockDim.x + threadIdx.x;
    if (idx >= NLYR * 256 * 128) return;
    int l  = idx >> 15;
    int r  = idx & 32767;
    int k  = r >> 7;
    int od = r & 127;
    float v = (k < 128) ? gw[l * 16384 + od * 128 + k]
                        : bw[l * 16384 + od * 128 + (k - 128)];
    g_wPack[idx] = v;
}

// ---------------------------------------------------------------------------
__global__ void init_copy(const float4* __restrict__ emb4, int n) {
    int i = blockIdx.x * blockDim.x + threadIdx.x;
    if (i >= n * 32) return;
    int node = i >> 5, d4 = i & 31;
    float4 v = emb4[i];
    ((float4*)g_all)[(size_t)node * 128 + d4] = v;
    ((float4*)g_ego)[i] = v;
    if (d4 == 0) { g_cnt[node] = 0; g_off[node] = 0; }
    if (i == 0) g_total = 0;
}

// ---------------------------------------------------------------------------
// CSR build: histogram -> hierarchical offset reservation -> scatter.
// ---------------------------------------------------------------------------
__global__ void csr_hist(const int* __restrict__ ei, int E) {
    int e = blockIdx.x * blockDim.x + threadIdx.x;
    if (e < E) atomicAdd(&g_cnt[ei[e]], 1);
}

__global__ __launch_bounds__(256) void csr_offsets(int n) {
    __shared__ int wbase[8];
    int tid  = threadIdx.x;
    int lane = tid & 31;
    int w    = tid >> 5;
    int i    = blockIdx.x * 256 + tid;
    int cnt  = (i < n) ? g_cnt[i] : 0;

    int pre = cnt;
#pragma unroll
    for (int off = 1; off < 32; off <<= 1) {
        int v = __shfl_up_sync(0xffffffffu, pre, off);
        if (lane >= off) pre += v;
    }
    if (lane == 31) wbase[w] = pre;
    __syncthreads();

    if (w == 0) {
        int orig = (lane < 8) ? wbase[lane] : 0;
        int s = orig;
#pragma unroll
        for (int off = 1; off < 8; off <<= 1) {
            int v = __shfl_up_sync(0xffffffffu, s, off);
            if (lane >= off) s += v;
        }
        int total = __shfl_sync(0xffffffffu, s, 7);
        int base = 0;
        if (lane == 7) base = atomicAdd(&g_total, total);
        base = __shfl_sync(0xffffffffu, base, 7);
        if (lane < 8) wbase[lane] = base + s - orig;
    }
    __syncthreads();

    if (i < n) g_rowptr[i] = wbase[w] + pre - cnt;
}

__global__ void csr_scatter(const int* __restrict__ ei,
                            const float* __restrict__ ew, int E) {
    int e = blockIdx.x * blockDim.x + threadIdx.x;
    if (e >= E) return;
    int row = ei[e];
    int col = ei[E + e];
    int pos = g_rowptr[row] + atomicAdd(&g_off[row], 1);
    g_ecol[pos] = col;
    g_ewc[pos]  = ew[e];
}

// ---------------------------------------------------------------------------
// SpMM via CSR: one warp per row, register accumulation, zero atomics.
// ---------------------------------------------------------------------------
__global__ void spmm_csr(int n) {
    int gt = blockIdx.x * blockDim.x + threadIdx.x;
    int row = gt >> 5, lane = gt & 31;
    if (row >= n) return;
    int beg = g_rowptr[row];
    int end = beg + g_cnt[row];
    float4 acc = make_float4(0.f, 0.f, 0.f, 0.f);
    for (int b = beg; b < end; b += 32) {
        int idx = b + lane;
        int c = 0; float w = 0.f;
        if (idx < end) { c = g_ecol[idx]; w = g_ewc[idx]; }
        int m = min(32, end - b);
        for (int j = 0; j < m; ++j) {
            int   cc = __shfl_sync(0xffffffffu, c, j);
            float ww = __shfl_sync(0xffffffffu, w, j);
            float4 v = ((const float4*)g_ego)[(size_t)cc * 32 + lane];
            acc.x += ww * v.x; acc.y += ww * v.y;
            acc.z += ww * v.z; acc.w += ww * v.w;
        }
    }
    ((float4*)g_msg)[(size_t)row * 32 + lane] = acc;
}

// ---------------------------------------------------------------------------
// Fused layer GEMM (R7 tile: 64 nodes x 128 ods, 2n x 8o per thread, f32x2)
// with register-prefetch double buffering: chunk c+1's LDGs issue before
// chunk c's compute, hiding global-load latency behind the 32-k FMA loop.
// ---------------------------------------------------------------------------
__global__ __launch_bounds__(512) void fused_layer(
        const float* __restrict__ gcb, const float* __restrict__ bib,
        int n, int layer) {
    __shared__ __align__(16) float As[32 * 65];    // [kc][node], pad 65
    __shared__ __align__(16) float Bs[32 * 128];   // [kc][od]
    __shared__ float invS[64];

    const int tid  = threadIdx.x;
    const int lane = tid & 31;
    const int w    = tid >> 5;         // 0..15
    const int odb  = w * 8;
    const int nb   = blockIdx.x * 64;
    const int loff = layer * 128;
    const float* wP = g_wPack + layer * 32768;

    // A-fill task (constant across chunks): one float4 of A per thread
    const int fk4   = tid & 7;         // k quad within chunk
    const int fnode = tid >> 3;        // 0..63
    const int fg    = nb + fnode;
    const bool fok  = (fg < n);

    unsigned long long acc[2][4];
#pragma unroll
    for (int i = 0; i < 2; ++i)
#pragma unroll
        for (int j = 0; j < 4; ++j) acc[i][j] = 0ull;

    // prefetch registers
    float4 pb0, pb1, pm;

    // ---- prologue: load chunk 0 ----
    {
        const float4* src = (const float4*)(wP);
        pb0 = src[tid];
        pb1 = src[tid + 512];
        int kk = fk4 * 4;              // chunk 0 -> kk < 128 always
        pm = fok ? *(const float4*)(g_msg + (size_t)fg * 128 + kk)
                 : make_float4(0.f, 0.f, 0.f, 0.f);
    }

    for (int c = 0; c < 8; ++c) {
        // ---- store prefetched chunk c into smem ----
        {
            float4* dst = (float4*)Bs;
            dst[tid]       = pb0;
            dst[tid + 512] = pb1;
            float* base = As + (fk4 * 4) * 65 + fnode;
            base[0]   = pm.x;
            base[65]  = pm.y;
            base[130] = pm.z;
            base[195] = pm.w;
        }
        __syncthreads();

        // ---- issue chunk c+1 LDGs (latency hidden by compute below) ----
        if (c < 7) {
            const float4* src = (const float4*)(wP + (c + 1) * 32 * 128);
            pb0 = src[tid];
            pb1 = src[tid + 512];
            int kk = (c + 1) * 32 + fk4 * 4;
            float4 m = make_float4(0.f, 0.f, 0.f, 0.f);
            if (fok) {
                if (kk < 128) {
                    m = *(const float4*)(g_msg + (size_t)fg * 128 + kk);
                } else {
                    m = *(const float4*)(g_msg + (size_t)fg * 128 + kk - 128);
                    float4 e = *(const float4*)(g_ego + (size_t)fg * 128 + kk - 128);
                    m.x *= e.x; m.y *= e.y; m.z *= e.z; m.w *= e.w;
                }
            }
            pm = m;
        }

        // ---- compute 32 k-steps on chunk c ----
#pragma unroll 8
        for (int k = 0; k < 32; ++k) {
            float a0 = As[k * 65 + lane];
            float a1 = As[k * 65 + 32 + lane];
            const ulonglong2* Bu = (const ulonglong2*)(Bs + k * 128 + odb);
            ulonglong2 b0 = Bu[0];     // ods odb..odb+3 (broadcast)
            ulonglong2 b1 = Bu[1];     // ods odb+4..odb+7
            unsigned long long p0 = pack2(a0);
            unsigned long long p1 = pack2(a1);
            fma2(acc[0][0], p0, b0.x); fma2(acc[0][1], p0, b0.y);
            fma2(acc[0][2], p0, b1.x); fma2(acc[0][3], p0, b1.y);
            fma2(acc[1][0], p1, b0.x); fma2(acc[1][1], p1, b0.y);
            fma2(acc[1][2], p1, b1.x); fma2(acc[1][3], p1, b1.y);
        }
        __syncthreads();
    }

    // --- epilogue ---
    float bias[8];
    {
        float4 bg0 = *(const float4*)(gcb + loff + odb);
        float4 bg1 = *(const float4*)(gcb + loff + odb + 4);
        float4 bb0 = *(const float4*)(bib + loff + odb);
        float4 bb1 = *(const float4*)(bib + loff + odb + 4);
        bias[0] = bg0.x + bb0.x; bias[1] = bg0.y + bb0.y;
        bias[2] = bg0.z + bb0.z; bias[3] = bg0.w + bb0.w;
        bias[4] = bg1.x + bb1.x; bias[5] = bg1.y + bb1.y;
        bias[6] = bg1.z + bb1.z; bias[7] = bg1.w + bb1.w;
    }

    float v[2][8];
    float s[2];
#pragma unroll
    for (int nn = 0; nn < 2; ++nn) {
        float sum = 0.f;
#pragma unroll
        for (int j = 0; j < 4; ++j) {
            float x0 = lo32(acc[nn][j]) + bias[2 * j];
            float x1 = hi32(acc[nn][j]) + bias[2 * j + 1];
            x0 = (x0 > 0.f) ? x0 : 0.2f * x0;
            x1 = (x1 > 0.f) ? x1 : 0.2f * x1;
            v[nn][2 * j]     = x0;
            v[nn][2 * j + 1] = x1;
            sum += x0 * x0 + x1 * x1;
        }
        s[nn] = sum;
    }

    // cross-warp L2-norm reduction: reuse As as red[16][64]
    As[w * 64 + lane]      = s[0];
    As[w * 64 + 32 + lane] = s[1];
    __syncthreads();
    if (tid < 64) {
        float t = 0.f;
#pragma unroll
        for (int ww = 0; ww < 16; ++ww) t += As[ww * 64 + tid];
        invS[tid] = 1.0f / fmaxf(sqrtf(t), 1e-12f);
    }
    __syncthreads();

#pragma unroll
    for (int nn = 0; nn < 2; ++nn) {
        int node = lane + 32 * nn;
        int g = nb + node;
        if (g < n) {
            float inv = invS[node];
            float4 w0 = make_float4(v[nn][0], v[nn][1], v[nn][2], v[nn][3]);
            float4 w1 = make_float4(v[nn][4], v[nn][5], v[nn][6], v[nn][7]);
            *(float4*)(g_ego + (size_t)g * 128 + odb)     = w0;
            *(float4*)(g_ego + (size_t)g * 128 + odb + 4) = w1;
            *(float4*)(g_all + (size_t)g * 512 + loff + 128 + odb) =
                make_float4(w0.x * inv, w0.y * inv, w0.z * inv, w0.w * inv);
            *(float4*)(g_all + (size_t)g * 512 + loff + 128 + odb + 4) =
                make_float4(w1.x * inv, w1.y * inv, w1.z * inv, w1.w * inv);
        }
    }
}

// ---------------------------------------------------------------------------
// Scoring: out[q] = dot(all[src[q]], all[dst[q]]) over 512 dims. Warp/query.
// ---------------------------------------------------------------------------
__global__ void score(const int* __restrict__ eli, int Q,
                      float* __restrict__ out) {
    int gt = blockIdx.x * blockDim.x + threadIdx.x;
    int q = gt >> 5, lane = gt & 31;
    if (q >= Q) return;
    int s = eli[q];
    int d = eli[Q + q];
    const float4* a = (const float4*)(g_all + (size_t)s * 512);
    const float4* b = (const float4*)(g_all + (size_t)d * 512);
    float acc = 0.f;
#pragma unroll
    for (int j = 0; j < 4; ++j) {
        float4 x = a[lane + 32 * j];
        float4 y = b[lane + 32 * j];
        acc += x.x * y.x + x.y * y.y + x.z * y.z + x.w * y.w;
    }
#pragma unroll
    for (int off = 16; off; off >>= 1)
        acc += __shfl_xor_sync(0xffffffffu, acc, off);
    if (lane == 0) out[q] = acc;
}

// ---------------------------------------------------------------------------
extern "C" void kernel_launch(void* const* d_in, const int* in_sizes, int n_in,
                              void* d_out, int out_size) {
    const int*   ei  = (const int*)d_in[0];
    const int*   eli = (const int*)d_in[1];
    const float* ew  = (const float*)d_in[2];
    const float* emb = (const float*)d_in[3];
    const float* gcw = (const float*)d_in[4];
    const float* gcb = (const float*)d_in[5];
    const float* biw = (const float*)d_in[6];
    const float* bib = (const float*)d_in[7];

    int E = in_sizes[0] / 2;
    int Q = in_sizes[1] / 2;
    int n = in_sizes[3] / 128;
    float* out = (float*)d_out;

    pack_weights<<<(NLYR * 256 * 128 + 255) / 256, 256>>>(gcw, biw);
    init_copy<<<(n * 32 + 255) / 256, 256>>>((const float4*)emb, n);

    csr_hist<<<(E + 255) / 256, 256>>>(ei, E);
    csr_offsets<<<(n + 255) / 256, 256>>>(n);
    csr_scatter<<<(E + 255) / 256, 256>>>(ei, ew, E);

    for (int l = 0; l < NLYR; ++l) {
        spmm_csr<<<(int)(((size_t)n * 32 + 255) / 256), 256>>>(n);
        fused_layer<<<(n + 63) / 64, 512>>>(gcb, bib, n, l);
    }

    score<<<(int)(((size_t)Q * 32 + 255) / 256), 256>>>(eli, Q, out);
}

// round 11
// speedup vs baseline: 1.8314x; 1.5724x over previous
#include <cuda_runtime.h>
#include <cstdint>

#define NMAX 100000
#define EMAX 1600000
#define NLYR 3

// Device scratch.
__device__ __align__(16) float g_all[(size_t)NMAX * 512];
__device__ __align__(16) float g_ego[(size_t)NMAX * 128];
__device__ __align__(16) float g_msg[(size_t)NMAX * 128];
// Pre-split bf16 weights: [l][chunk 0..7][hi/lo][od 0..127][k 0..31]
__device__ __align__(16) unsigned short g_wbf[NLYR * 8 * 2 * 128 * 32];
// CSR built once per launch.
__device__ int   g_rowptr[NMAX];
__device__ int   g_cnt[NMAX];
__device__ int   g_off[NMAX];
__device__ int   g_total;
__device__ int   g_ecol[EMAX];
__device__ float g_ewc[EMAX];

// ---------------------------------------------------------------------------
__device__ __forceinline__ uint32_t smem_to_u32(const void* p) {
    uint32_t a;
    asm("{ .reg .u64 t; cvta.to.shared.u64 t, %1; cvt.u32.u64 %0, t; }"
        : "=r"(a) : "l"(p));
    return a;
}
// pack two floats to bf16x2 (a -> upper, b -> lower)
__device__ __forceinline__ uint32_t bf16x2_of(float a, float b) {
    uint32_t r;
    asm("cvt.rn.bf16x2.f32 %0, %1, %2;" : "=r"(r) : "f"(a), "f"(b));
    return r;
}
__device__ __forceinline__ void ldmx4(uint32_t* r, uint32_t addr) {
    asm volatile("ldmatrix.sync.aligned.m8n8.x4.shared.b16 {%0,%1,%2,%3}, [%4];"
                 : "=r"(r[0]), "=r"(r[1]), "=r"(r[2]), "=r"(r[3]) : "r"(addr));
}
__device__ __forceinline__ void mma_bf16(float* c, const uint32_t* a,
                                         const uint32_t* b) {
    asm volatile(
        "mma.sync.aligned.m16n8k16.row.col.f32.bf16.bf16.f32 "
        "{%0,%1,%2,%3}, {%4,%5,%6,%7}, {%8,%9}, {%0,%1,%2,%3};"
        : "+f"(c[0]), "+f"(c[1]), "+f"(c[2]), "+f"(c[3])
        : "r"(a[0]), "r"(a[1]), "r"(a[2]), "r"(a[3]), "r"(b[0]), "r"(b[1]));
}

// ---------------------------------------------------------------------------
// pack_weights: stacked [gc_w | bi_w] K=256, split to bf16 hi+lo.
// ---------------------------------------------------------------------------
__global__ void pack_weights(const float* __restrict__ gw,
                             const float* __restrict__ bw) {
    int idx = blockIdx.x * blockDim.x + threadIdx.x;
    if (idx >= NLYR * 128 * 256) return;
    int l  = idx >> 15;
    int r  = idx & 32767;
    int od = r >> 8;
    int k  = r & 255;
    float x = (k < 128) ? gw[l * 16384 + od * 128 + k]
                        : bw[l * 16384 + od * 128 + (k - 128)];
    uint32_t h2 = bf16x2_of(x, x);
    float xh = __uint_as_float(h2 & 0xffff0000u);
    uint32_t l2 = bf16x2_of(x - xh, x - xh);
    int c = k >> 5, q = k & 31;
    size_t base = ((size_t)((l * 8 + c) * 2) * 128 + od) * 32 + q;
    g_wbf[base]            = (unsigned short)(h2 >> 16);
    g_wbf[base + 128 * 32] = (unsigned short)(l2 >> 16);
}

// ---------------------------------------------------------------------------
__global__ void init_copy(const float4* __restrict__ emb4, int n) {
    int i = blockIdx.x * blockDim.x + threadIdx.x;
    if (i >= n * 32) return;
    int node = i >> 5, d4 = i & 31;
    float4 v = emb4[i];
    ((float4*)g_all)[(size_t)node * 128 + d4] = v;
    ((float4*)g_ego)[i] = v;
    if (d4 == 0) { g_cnt[node] = 0; g_off[node] = 0; }
    if (i == 0) g_total = 0;
}

// ---------------------------------------------------------------------------
// CSR build (proven R9 path).
// ---------------------------------------------------------------------------
__global__ void csr_hist(const int* __restrict__ ei, int E) {
    int e = blockIdx.x * blockDim.x + threadIdx.x;
    if (e < E) atomicAdd(&g_cnt[ei[e]], 1);
}

__global__ __launch_bounds__(256) void csr_offsets(int n) {
    __shared__ int wbase[8];
    int tid  = threadIdx.x;
    int lane = tid & 31;
    int w    = tid >> 5;
    int i    = blockIdx.x * 256 + tid;
    int cnt  = (i < n) ? g_cnt[i] : 0;

    int pre = cnt;
#pragma unroll
    for (int off = 1; off < 32; off <<= 1) {
        int v = __shfl_up_sync(0xffffffffu, pre, off);
        if (lane >= off) pre += v;
    }
    if (lane == 31) wbase[w] = pre;
    __syncthreads();
    if (w == 0) {
        int orig = (lane < 8) ? wbase[lane] : 0;
        int s = orig;
#pragma unroll
        for (int off = 1; off < 8; off <<= 1) {
            int v = __shfl_up_sync(0xffffffffu, s, off);
            if (lane >= off) s += v;
        }
        int total = __shfl_sync(0xffffffffu, s, 7);
        int base = 0;
        if (lane == 7) base = atomicAdd(&g_total, total);
        base = __shfl_sync(0xffffffffu, base, 7);
        if (lane < 8) wbase[lane] = base + s - orig;
    }
    __syncthreads();
    if (i < n) g_rowptr[i] = wbase[w] + pre - cnt;
}

__global__ void csr_scatter(const int* __restrict__ ei,
                            const float* __restrict__ ew, int E) {
    int e = blockIdx.x * blockDim.x + threadIdx.x;
    if (e >= E) return;
    int row = ei[e];
    int col = ei[E + e];
    int pos = g_rowptr[row] + atomicAdd(&g_off[row], 1);
    g_ecol[pos] = col;
    g_ewc[pos]  = ew[e];
}

// ---------------------------------------------------------------------------
// SpMM via CSR (proven, at gather roof).
// ---------------------------------------------------------------------------
__global__ void spmm_csr(int n) {
    int gt = blockIdx.x * blockDim.x + threadIdx.x;
    int row = gt >> 5, lane = gt & 31;
    if (row >= n) return;
    int beg = g_rowptr[row];
    int end = beg + g_cnt[row];
    float4 acc = make_float4(0.f, 0.f, 0.f, 0.f);
    for (int b = beg; b < end; b += 32) {
        int idx = b + lane;
        int c = 0; float w = 0.f;
        if (idx < end) { c = g_ecol[idx]; w = g_ewc[idx]; }
        int m = min(32, end - b);
        for (int j = 0; j < m; ++j) {
            int   cc = __shfl_sync(0xffffffffu, c, j);
            float ww = __shfl_sync(0xffffffffu, w, j);
            float4 v = ((const float4*)g_ego)[(size_t)cc * 32 + lane];
            acc.x += ww * v.x; acc.y += ww * v.y;
            acc.z += ww * v.z; acc.w += ww * v.w;
        }
    }
    ((float4*)g_msg)[(size_t)row * 32 + lane] = acc;
}

// ---------------------------------------------------------------------------
// Fused layer via warp-level split-bf16 HMMA (mma.sync m16n8k16).
//   C[64 nodes][128 od] = A[64][256] * W[128][256]^T
//   A = [msg | ego*msg] fp32, split to bf16 hi/lo on the fly.
//   3 terms: Ah*Wh + Ah*Wl + Al*Wh, fp32 accumulate in registers.
// Block 256 thr / 8 warps; warp (wm = w>>2, wn = w&3) owns m32 x n32.
// Smem tiles (pitch 40 shorts = 80B, ldmatrix conflict-free):
//   A hi/lo: 64x32 bf16 (5120B each); W hi/lo: 128x32 bf16 (10240B each).
// Epilogue overlays Vs[64][132] fp32 on the same buffer.
// ---------------------------------------------------------------------------
#define PITCH 40                   // shorts per row (80 bytes)
#define SA_H 0
#define SA_L 5120
#define SW_H 10240
#define SW_L 20480
#define SBUF_BYTES 33792           // max(30720 tiles, 64*132*4 Vs)

__global__ __launch_bounds__(256) void fused_layer_mma(
        const float* __restrict__ gcb, const float* __restrict__ bib,
        int n, int layer) {
    __shared__ __align__(16) char sbuf[SBUF_BYTES];
    __shared__ float biasS[128];
    __shared__ float part[64];
    __shared__ float invS[64];

    const int tid  = threadIdx.x;
    const int lane = tid & 31;
    const int w    = tid >> 5;
    const int wm   = w >> 2;           // 0..1  -> m32 block
    const int wn   = w & 3;            // 0..3  -> n32 block
    const int m0   = wm * 32;
    const int n0   = wn * 32;
    const int nb   = blockIdx.x * 64;
    const int loff = layer * 128;
    const uint32_t sb = smem_to_u32(sbuf);

    if (tid < 128) biasS[tid] = gcb[loff + tid] + bib[loff + tid];
    if (tid < 64)  part[tid] = 0.f;

    float acc[2][4][4];
#pragma unroll
    for (int a = 0; a < 2; ++a)
#pragma unroll
        for (int b = 0; b < 4; ++b)
#pragma unroll
            for (int c = 0; c < 4; ++c) acc[a][b][c] = 0.f;

    const unsigned short* wsrc =
        g_wbf + (size_t)layer * 8 * 2 * 128 * 32;

    for (int c = 0; c < 8; ++c) {          // K chunks of 32
        __syncthreads();
        // ---- W fill: hi+lo tiles, 1024 uint4 over 256 threads ----
        {
            const uint4* src = (const uint4*)(wsrc + (size_t)(c * 2) * 128 * 32);
#pragma unroll
            for (int i = 0; i < 4; ++i) {
                int idx = tid + 256 * i;        // 0..1023
                int h   = idx >> 9;             // 0 hi, 1 lo
                int rem = idx & 511;
                int row = rem >> 2;
                int seg = rem & 3;
                uint4 v = src[idx];             // contiguous [h][row][seg]
                *(uint4*)(sbuf + (h ? SW_L : SW_H) + row * (PITCH * 2) + seg * 16) = v;
            }
        }
        // ---- A fill: 512 float4 tasks (64 nodes x 8 quads), split hi/lo ----
#pragma unroll
        for (int i = 0; i < 2; ++i) {
            int idx  = tid + 256 * i;           // 0..511
            int node = idx >> 3;
            int q    = idx & 7;
            int g    = nb + node;
            float4 x = make_float4(0.f, 0.f, 0.f, 0.f);
            if (g < n) {
                if (c < 4) {
                    x = *(const float4*)(g_msg + (size_t)g * 128 + c * 32 + q * 4);
                } else {
                    int kk = (c - 4) * 32 + q * 4;
                    float4 m = *(const float4*)(g_msg + (size_t)g * 128 + kk);
                    float4 e = *(const float4*)(g_ego + (size_t)g * 128 + kk);
                    x = make_float4(m.x * e.x, m.y * e.y, m.z * e.z, m.w * e.w);
                }
            }
            uint32_t h01 = bf16x2_of(x.y, x.x);   // upper=y, lower=x
            uint32_t h23 = bf16x2_of(x.w, x.z);
            float a0 = __uint_as_float(h01 << 16);
            float a1 = __uint_as_float(h01 & 0xffff0000u);
            float a2 = __uint_as_float(h23 << 16);
            float a3 = __uint_as_float(h23 & 0xffff0000u);
            uint32_t l01 = bf16x2_of(x.y - a1, x.x - a0);
            uint32_t l23 = bf16x2_of(x.w - a3, x.z - a2);
            *(uint2*)(sbuf + SA_H + node * (PITCH * 2) + q * 8) = make_uint2(h01, h23);
            *(uint2*)(sbuf + SA_L + node * (PITCH * 2) + q * 8) = make_uint2(l01, l23);
        }
        __syncthreads();

        // ---- compute: 2 k16 steps ----
#pragma unroll
        for (int kb = 0; kb < 2; ++kb) {
            uint32_t Ah[2][4], Al[2][4], Wh[2][4], Wl[2][4];
            // A frags: m16k16, lanes 0-15 rows(k0-7 half), 16-31 second 16B
            {
                int arow = lane & 15;
                uint32_t aoff = (uint32_t)((lane >> 4) * 16 + kb * 32);
#pragma unroll
                for (int mt = 0; mt < 2; ++mt) {
                    uint32_t ra = sb + SA_H +
                        (uint32_t)(m0 + mt * 16 + arow) * (PITCH * 2) + aoff;
                    ldmx4(Ah[mt], ra);
                    ldmx4(Al[mt], ra + (SA_L - SA_H));
                }
            }
            // W frags: two n8k16 tiles per x4
            {
                int g = lane >> 3, r = lane & 7;
                int wrow = n0 + r + ((g >> 1) << 3);
                uint32_t woff = (uint32_t)((g & 1) * 16 + kb * 32);
#pragma unroll
                for (int nt2 = 0; nt2 < 2; ++nt2) {
                    uint32_t rw = sb + SW_H +
                        (uint32_t)(wrow + nt2 * 16) * (PITCH * 2) + woff;
                    ldmx4(Wh[nt2], rw);
                    ldmx4(Wl[nt2], rw + (SW_L - SW_H));
                }
            }
#pragma unroll
            for (int mt = 0; mt < 2; ++mt) {
#pragma unroll
                for (int nt = 0; nt < 4; ++nt) {
                    const uint32_t* bh = &Wh[nt >> 1][(nt & 1) * 2];
                    const uint32_t* bl = &Wl[nt >> 1][(nt & 1) * 2];
                    mma_bf16(acc[mt][nt], Ah[mt], bh);
                    mma_bf16(acc[mt][nt], Ah[mt], bl);
                    mma_bf16(acc[mt][nt], Al[mt], bh);
                }
            }
        }
    }
    __syncthreads();   // tiles dead; Vs overlays sbuf

    // ---- epilogue: bias + leaky_relu into Vs, per-row ssq ----
    float* Vs = (float*)sbuf;          // [64][132]
    float rs[2][2] = {{0.f, 0.f}, {0.f, 0.f}};
#pragma unroll
    for (int mt = 0; mt < 2; ++mt) {
#pragma unroll
        for (int nt = 0; nt < 4; ++nt) {
            int row0 = m0 + mt * 16 + (lane >> 2);
            int col  = n0 + nt * 8 + (lane & 3) * 2;
            float b0 = biasS[col], b1 = biasS[col + 1];
            float x0 = acc[mt][nt][0] + b0;
            float x1 = acc[mt][nt][1] + b1;
            float x2 = acc[mt][nt][2] + b0;
            float x3 = acc[mt][nt][3] + b1;
            x0 = (x0 > 0.f) ? x0 : 0.2f * x0;
            x1 = (x1 > 0.f) ? x1 : 0.2f * x1;
            x2 = (x2 > 0.f) ? x2 : 0.2f * x2;
            x3 = (x3 > 0.f) ? x3 : 0.2f * x3;
            Vs[row0 * 132 + col]           = x0;
            Vs[row0 * 132 + col + 1]       = x1;
            Vs[(row0 + 8) * 132 + col]     = x2;
            Vs[(row0 + 8) * 132 + col + 1] = x3;
            rs[mt][0] += x0 * x0 + x1 * x1;
            rs[mt][1] += x2 * x2 + x3 * x3;
        }
    }
#pragma unroll
    for (int mt = 0; mt < 2; ++mt)
#pragma unroll
        for (int hh = 0; hh < 2; ++hh) {
            float v = rs[mt][hh];
            v += __shfl_xor_sync(0xffffffffu, v, 1);
            v += __shfl_xor_sync(0xffffffffu, v, 2);
            if ((lane & 3) == 0)
                atomicAdd(&part[m0 + mt * 16 + hh * 8 + (lane >> 2)], v);
        }
    __syncthreads();
    if (tid < 64) invS[tid] = 1.0f / fmaxf(sqrtf(part[tid]), 1e-12f);
    __syncthreads();

    // ---- writeout: coalesced float4 ----
    for (int i = tid; i < 64 * 32; i += 256) {
        int node = i >> 5, d4 = i & 31;
        int g = nb + node;
        if (g < n) {
            const float* p = Vs + node * 132 + d4 * 4;
            float inv = invS[node];
            float4 v = make_float4(p[0], p[1], p[2], p[3]);
            *(float4*)(g_ego + (size_t)g * 128 + d4 * 4) = v;
            *(float4*)(g_all + (size_t)g * 512 + loff + 128 + d4 * 4) =
                make_float4(v.x * inv, v.y * inv, v.z * inv, v.w * inv);
        }
    }
}

// ---------------------------------------------------------------------------
// Scoring (unchanged).
// ---------------------------------------------------------------------------
__global__ void score(const int* __restrict__ eli, int Q,
                      float* __restrict__ out) {
    int gt = blockIdx.x * blockDim.x + threadIdx.x;
    int q = gt >> 5, lane = gt & 31;
    if (q >= Q) return;
    int s = eli[q];
    int d = eli[Q + q];
    const float4* a = (const float4*)(g_all + (size_t)s * 512);
    const float4* b = (const float4*)(g_all + (size_t)d * 512);
    float acc = 0.f;
#pragma unroll
    for (int j = 0; j < 4; ++j) {
        float4 x = a[lane + 32 * j];
        float4 y = b[lane + 32 * j];
        acc += x.x * y.x + x.y * y.y + x.z * y.z + x.w * y.w;
    }
#pragma unroll
    for (int off = 16; off; off >>= 1)
        acc += __shfl_xor_sync(0xffffffffu, acc, off);
    if (lane == 0) out[q] = acc;
}

// ---------------------------------------------------------------------------
extern "C" void kernel_launch(void* const* d_in, const int* in_sizes, int n_in,
                              void* d_out, int out_size) {
    const int*   ei  = (const int*)d_in[0];
    const int*   eli = (const int*)d_in[1];
    const float* ew  = (const float*)d_in[2];
    const float* emb = (const float*)d_in[3];
    const float* gcw = (const float*)d_in[4];
    const float* gcb = (const float*)d_in[5];
    const float* biw = (const float*)d_in[6];
    const float* bib = (const float*)d_in[7];

    int E = in_sizes[0] / 2;
    int Q = in_sizes[1] / 2;
    int n = in_sizes[3] / 128;
    float* out = (float*)d_out;

    pack_weights<<<(NLYR * 128 * 256 + 255) / 256, 256>>>(gcw, biw);
    init_copy<<<(n * 32 + 255) / 256, 256>>>((const float4*)emb, n);

    csr_hist<<<(E + 255) / 256, 256>>>(ei, E);
    csr_offsets<<<(n + 255) / 256, 256>>>(n);
    csr_scatter<<<(E + 255) / 256, 256>>>(ei, ew, E);

    for (int l = 0; l < NLYR; ++l) {
        spmm_csr<<<(int)(((size_t)n * 32 + 255) / 256), 256>>>(n);
        fused_layer_mma<<<(n + 63) / 64, 256>>>(gcb, bib, n, l);
    }

    score<<<(int)(((size_t)Q * 32 + 255) / 256), 256>>>(eli, Q, out);
}